// round 11
// baseline (speedup 1.0000x reference)
#include <cuda_runtime.h>
#include <math.h>

#define N_NODES 50000
#define F_IN    128
#define H1      128
#define H2      64
#define E_TRAIN 600000
#define E_SCORE 200000
#define NB_SCAN 196                     // ceil(50000/256)

// Scratch buffers (device globals — no allocation allowed; zero-initialized)
__device__ float g_dinv  [N_NODES];
__device__ int   g_cnt   [N_NODES];               // in-degree; self-zeroed by k_scan
__device__ int   g_rowptr[N_NODES + 1];
__device__ int   g_cursor[N_NODES];
__device__ int   g_ticket;                        // lookback ticket; reset by k_fill
__device__ unsigned long long g_lb[256];          // lookback words (prefix<<2 | status); reset by k_fill
__device__ int   g_esrc  [E_TRAIN];
__device__ float g_h0    [N_NODES * H1];
__device__ float g_agg1  [N_NODES * H1];
__device__ float g_h2p   [N_NODES * H2];
__device__ float g_agg2  [N_NODES * H2];

// ---------------------------------------------------------------- count (cnt arrives zeroed)
__global__ void k_count(const int* __restrict__ ei) {
    int e = blockIdx.x * blockDim.x + threadIdx.x;
    if (e < E_TRAIN) atomicAdd(&g_cnt[ei[E_TRAIN + e]], 1);   // col = target
}

// ---------------------------------------------------------------- single-kernel scan (decoupled lookback)
// Produces final g_rowptr/g_cursor, g_dinv; self-zeros g_cnt for the next replay.
__global__ __launch_bounds__(256) void k_scan() {
    __shared__ int wsum[8];
    __shared__ int sh_bid;
    __shared__ int sh_total;
    __shared__ int sh_exc;
    int t = threadIdx.x;
    if (t == 0) sh_bid = atomicAdd(&g_ticket, 1);
    __syncthreads();
    int bid = sh_bid;
    int i   = bid * 256 + t;

    int v = 0;
    if (i < N_NODES) {
        v = g_cnt[i];
        g_cnt[i] = 0;                               // self-clean for next replay
        g_dinv[i] = rsqrtf((float)(v + 1));
    }
    // block-local inclusive scan
    int s = v;
#pragma unroll
    for (int o = 1; o < 32; o <<= 1) {
        int u = __shfl_up_sync(0xFFFFFFFFu, s, o);
        if ((t & 31) >= o) s += u;
    }
    if ((t & 31) == 31) wsum[t >> 5] = s;
    __syncthreads();
    if (t < 8) {
        int w = wsum[t];
        int e = w;
#pragma unroll
        for (int o = 1; o < 8; o <<= 1) {
            int u = __shfl_up_sync(0xFFu, e, o);
            if (t >= o) e += u;
        }
        wsum[t] = e - w;                            // exclusive warp offsets
    }
    __syncthreads();
    int incl = s + wsum[t >> 5];
    if (t == 255) sh_total = incl;
    __syncthreads();
    int total = sh_total;

    if (t == 0) {
        unsigned long long exc = 0;
        if (bid > 0) {
            // publish aggregate early so successors can hop over us
            atomicExch(&g_lb[bid], ((unsigned long long)total << 2) | 1ull);
            int j = bid - 1;
            while (true) {
                unsigned long long w = atomicAdd(&g_lb[j], 0ull);
                unsigned st = (unsigned)(w & 3ull);
                if (st == 2u) { exc += (w >> 2); break; }
                if (st == 1u) { exc += (w >> 2); j--; }
            }
        }
        atomicExch(&g_lb[bid], ((exc + (unsigned long long)total) << 2) | 2ull);
        sh_exc = (int)exc;
    }
    __syncthreads();
    int exc = sh_exc;
    if (i < N_NODES) {
        int r = exc + incl - v;                     // global exclusive
        g_rowptr[i] = r;
        g_cursor[i] = r;
    }
    if (i == 0) g_rowptr[N_NODES] = E_TRAIN;
}

// ---------------------------------------------------------------- fill (+ reset lookback state for next replay)
__global__ void k_fill(const int* __restrict__ ei) {
    int gt = blockIdx.x * blockDim.x + threadIdx.x;
    if (blockIdx.x == 0) {
        if (threadIdx.x < NB_SCAN) g_lb[threadIdx.x] = 0ull;
        if (threadIdx.x == NB_SCAN) g_ticket = 0;
    }
    if (gt >= E_TRAIN) return;
    int dst = ei[E_TRAIN + gt];
    int p = atomicAdd(&g_cursor[dst], 1);
    g_esrc[p] = ei[gt];
}

// ---------------------------------------------------------------- GEMM1: g_h0 = x @ W1  [50000x128]@[128x128]
// Block tile 64x128, 256 threads (16 tr x 16 tc), thread tile 4x8 (contiguous cols tc*8).
// Full W (64KB) + full 64x128 x-tile (32KB, transposed to [kk][row]) staged once; ONE sync.
#define G1_SMEM (128 * 128 * 4 + 128 * 64 * 4)   // 98304
__global__ __launch_bounds__(256) void k_gemm1(const float* __restrict__ x,
                                               const float* __restrict__ W) {
    extern __shared__ float sm[];
    float* Ws = sm;                     // [kk][col], stride 128
    float* xs = sm + 128 * 128;         // [kk][row], stride 64
    const int tx   = threadIdx.x;
    const int tr   = tx >> 4;           // rows tr*4..+3
    const int tc   = tx & 15;           // cols tc*8..+7
    const int row0 = blockIdx.x * 64;

    // stage W: 4096 float4, 16/thread (coalesced copy)
#pragma unroll
    for (int q = 0; q < 16; q++) {
        int idx = tx + 256 * q;
        ((float4*)Ws)[idx] = ((const float4*)W)[idx];
    }
    // stage x transposed: 2048 float4 reads -> scalar STS (conflict-free: consecutive rows)
#pragma unroll
    for (int q = 0; q < 8; q++) {
        int idx = tx + 256 * q;         // 0..2047
        int row = idx >> 5;             // 0..63
        int kc  = (idx & 31) * 4;
        float4 v = make_float4(0.f, 0.f, 0.f, 0.f);
        int grow = row0 + row;
        if (grow < N_NODES) v = *(const float4*)&x[grow * F_IN + kc];
        xs[(kc + 0) * 64 + row] = v.x;
        xs[(kc + 1) * 64 + row] = v.y;
        xs[(kc + 2) * 64 + row] = v.z;
        xs[(kc + 3) * 64 + row] = v.w;
    }
    __syncthreads();

    float acc[4][8];
#pragma unroll
    for (int r = 0; r < 4; r++)
#pragma unroll
        for (int j = 0; j < 8; j++) acc[r][j] = 0.0f;

#pragma unroll 8
    for (int kk = 0; kk < 128; kk++) {
        float4 xa = *(const float4*)&xs[kk * 64 + tr * 4];
        float4 w0 = *(const float4*)&Ws[kk * 128 + tc * 8];
        float4 w1 = *(const float4*)&Ws[kk * 128 + tc * 8 + 4];
        float xv[4] = { xa.x, xa.y, xa.z, xa.w };
        float wv[8] = { w0.x, w0.y, w0.z, w0.w, w1.x, w1.y, w1.z, w1.w };
#pragma unroll
        for (int r = 0; r < 4; r++)
#pragma unroll
            for (int j = 0; j < 8; j++)
                acc[r][j] += xv[r] * wv[j];
    }

#pragma unroll
    for (int r = 0; r < 4; r++) {
        int grow = row0 + tr * 4 + r;
        if (grow < N_NODES) {
            float* o = &g_h0[grow * H1 + tc * 8];
            *(float4*)(o + 0) = make_float4(acc[r][0], acc[r][1], acc[r][2], acc[r][3]);
            *(float4*)(o + 4) = make_float4(acc[r][4], acc[r][5], acc[r][6], acc[r][7]);
        }
    }
}

// ---------------------------------------------------------------- agg1 gather: warp per node, 128 feats, unroll 2
__global__ __launch_bounds__(256) void k_agg1_gather(const float* __restrict__ b1) {
    int node = (blockIdx.x * blockDim.x + threadIdx.x) >> 5;
    if (node >= N_NODES) return;
    int lane = threadIdx.x & 31;

    float di = g_dinv[node];
    float selfs = di * di;

    float4 acc = *(const float4*)&g_h0[node * H1 + lane * 4];
    float4 bb  = *(const float4*)&b1[lane * 4];
    acc.x = acc.x * selfs + bb.x;
    acc.y = acc.y * selfs + bb.y;
    acc.z = acc.z * selfs + bb.z;
    acc.w = acc.w * selfs + bb.w;

    int s = g_rowptr[node];
    int e = g_rowptr[node + 1];
    int k = s;
    for (; k + 1 < e; k += 2) {
        int s0 = g_esrc[k], s1 = g_esrc[k + 1];
        float n0 = di * g_dinv[s0];
        float n1 = di * g_dinv[s1];
        float4 v0 = *(const float4*)&g_h0[s0 * H1 + lane * 4];
        float4 v1 = *(const float4*)&g_h0[s1 * H1 + lane * 4];
        acc.x += v0.x * n0 + v1.x * n1;
        acc.y += v0.y * n0 + v1.y * n1;
        acc.z += v0.z * n0 + v1.z * n1;
        acc.w += v0.w * n0 + v1.w * n1;
    }
    if (k < e) {
        int s0 = g_esrc[k];
        float n0 = di * g_dinv[s0];
        float4 v0 = *(const float4*)&g_h0[s0 * H1 + lane * 4];
        acc.x += v0.x * n0; acc.y += v0.y * n0;
        acc.z += v0.z * n0; acc.w += v0.w * n0;
    }
    *(float4*)&g_agg1[node * H1 + lane * 4] = acc;
}

// ---------------------------------------------------------------- GEMM2: g_h2p = relu(g_agg1) @ W2  [50000x128]@[128x64]
// Block tile 64x64, thread tile 4x4. Full W2 (32KB) + x-tile (32KB); ONE sync; ReLU fused.
#define G2_SMEM (128 * 64 * 4 + 128 * 64 * 4)    // 65536
__global__ __launch_bounds__(256) void k_gemm2(const float* __restrict__ W2) {
    extern __shared__ float sm[];
    float* Ws = sm;                     // [kk][col], stride 64
    float* xs = sm + 128 * 64;          // [kk][row], stride 64
    const int tx   = threadIdx.x;
    const int tr   = tx >> 4;
    const int tc   = tx & 15;           // cols tc*4..+3
    const int row0 = blockIdx.x * 64;

    // stage W2: 2048 float4, 8/thread
#pragma unroll
    for (int q = 0; q < 8; q++) {
        int idx = tx + 256 * q;
        ((float4*)Ws)[idx] = ((const float4*)W2)[idx];
    }
    // stage x = relu(g_agg1), transposed
#pragma unroll
    for (int q = 0; q < 8; q++) {
        int idx = tx + 256 * q;
        int row = idx >> 5;
        int kc  = (idx & 31) * 4;
        float4 v = make_float4(0.f, 0.f, 0.f, 0.f);
        int grow = row0 + row;
        if (grow < N_NODES) v = *(const float4*)&g_agg1[grow * H1 + kc];
        xs[(kc + 0) * 64 + row] = fmaxf(v.x, 0.f);
        xs[(kc + 1) * 64 + row] = fmaxf(v.y, 0.f);
        xs[(kc + 2) * 64 + row] = fmaxf(v.z, 0.f);
        xs[(kc + 3) * 64 + row] = fmaxf(v.w, 0.f);
    }
    __syncthreads();

    float acc[4][4];
#pragma unroll
    for (int r = 0; r < 4; r++)
#pragma unroll
        for (int j = 0; j < 4; j++) acc[r][j] = 0.0f;

#pragma unroll 8
    for (int kk = 0; kk < 128; kk++) {
        float4 xa = *(const float4*)&xs[kk * 64 + tr * 4];
        float4 wb = *(const float4*)&Ws[kk * 64 + tc * 4];
        float xv[4] = { xa.x, xa.y, xa.z, xa.w };
        float wv[4] = { wb.x, wb.y, wb.z, wb.w };
#pragma unroll
        for (int r = 0; r < 4; r++)
#pragma unroll
            for (int j = 0; j < 4; j++)
                acc[r][j] += xv[r] * wv[j];
    }

#pragma unroll
    for (int r = 0; r < 4; r++) {
        int grow = row0 + tr * 4 + r;
        if (grow < N_NODES)
            *(float4*)&g_h2p[grow * H2 + tc * 4] =
                make_float4(acc[r][0], acc[r][1], acc[r][2], acc[r][3]);
    }
}

// ---------------------------------------------------------------- agg2 gather: half-warp per node, 64 feats, unroll 2
__global__ __launch_bounds__(256) void k_agg2_gather(const float* __restrict__ b2) {
    int node = (blockIdx.x * blockDim.x + threadIdx.x) >> 4;
    if (node >= N_NODES) return;
    int lane = threadIdx.x & 15;

    float di = g_dinv[node];
    float selfs = di * di;

    float4 acc = *(const float4*)&g_h2p[node * H2 + lane * 4];
    float4 bb  = *(const float4*)&b2[lane * 4];
    acc.x = acc.x * selfs + bb.x;
    acc.y = acc.y * selfs + bb.y;
    acc.z = acc.z * selfs + bb.z;
    acc.w = acc.w * selfs + bb.w;

    int s = g_rowptr[node];
    int e = g_rowptr[node + 1];
    int k = s;
    for (; k + 1 < e; k += 2) {
        int s0 = g_esrc[k], s1 = g_esrc[k + 1];
        float n0 = di * g_dinv[s0];
        float n1 = di * g_dinv[s1];
        float4 v0 = *(const float4*)&g_h2p[s0 * H2 + lane * 4];
        float4 v1 = *(const float4*)&g_h2p[s1 * H2 + lane * 4];
        acc.x += v0.x * n0 + v1.x * n1;
        acc.y += v0.y * n0 + v1.y * n1;
        acc.z += v0.z * n0 + v1.z * n1;
        acc.w += v0.w * n0 + v1.w * n1;
    }
    if (k < e) {
        int s0 = g_esrc[k];
        float n0 = di * g_dinv[s0];
        float4 v0 = *(const float4*)&g_h2p[s0 * H2 + lane * 4];
        acc.x += v0.x * n0; acc.y += v0.y * n0;
        acc.z += v0.z * n0; acc.w += v0.w * n0;
    }
    *(float4*)&g_agg2[node * H2 + lane * 4] = acc;
}

// ---------------------------------------------------------------- score: half-warp per edge, dot over 64 dims
__global__ __launch_bounds__(256) void k_score(const int* __restrict__ pos,
                                               const int* __restrict__ neg,
                                               float* __restrict__ out) {
    int w = (blockIdx.x * blockDim.x + threadIdx.x) >> 4;
    if (w >= 2 * E_SCORE) return;
    int lane = threadIdx.x & 15;
    int src, dst;
    if (w < E_SCORE) { src = pos[w];            dst = pos[E_SCORE + w]; }
    else             { int e = w - E_SCORE; src = neg[e]; dst = neg[E_SCORE + e]; }
    float4 a = *(const float4*)&g_agg2[src * H2 + lane * 4];
    float4 b = *(const float4*)&g_agg2[dst * H2 + lane * 4];
    float s = a.x * b.x + a.y * b.y + a.z * b.z + a.w * b.w;
#pragma unroll
    for (int o = 8; o; o >>= 1) s += __shfl_xor_sync(0xFFFFFFFFu, s, o);
    if (lane == 0) out[w] = s;
}

// ----------------------------------------------------------------
extern "C" void kernel_launch(void* const* d_in, const int* in_sizes, int n_in,
                              void* d_out, int out_size) {
    const float* x    = (const float*)d_in[0];
    const int*   tr   = (const int*)  d_in[1];   // [2, 600000]
    const int*   pos  = (const int*)  d_in[2];   // [2, 200000]
    const int*   neg  = (const int*)  d_in[3];   // [2, 200000]
    const float* W1   = (const float*)d_in[4];
    const float* b1   = (const float*)d_in[5];
    const float* W2   = (const float*)d_in[6];
    const float* b2   = (const float*)d_in[7];
    float* out = (float*)d_out;

    cudaFuncSetAttribute(k_gemm1, cudaFuncAttributeMaxDynamicSharedMemorySize, G1_SMEM);
    cudaFuncSetAttribute(k_gemm2, cudaFuncAttributeMaxDynamicSharedMemorySize, G2_SMEM);

    // CSR build (destination-sorted): count -> lookback scan -> fill
    k_count<<<(E_TRAIN + 255) / 256, 256>>>(tr);
    k_scan <<<NB_SCAN, 256>>>();
    k_fill <<<(E_TRAIN + 255) / 256, 256>>>(tr);

    // Layer 1
    k_gemm1<<<(N_NODES + 63) / 64, 256, G1_SMEM>>>(x, W1);
    k_agg1_gather<<<(N_NODES * 32 + 255) / 256, 256>>>(b1);

    // Layer 2
    k_gemm2<<<(N_NODES + 63) / 64, 256, G2_SMEM>>>(W2);
    k_agg2_gather<<<(N_NODES * 16 + 255) / 256, 256>>>(b2);

    // Scores
    k_score<<<(2 * E_SCORE * 16 + 255) / 256, 256>>>(pos, neg, out);
}

// round 14
// speedup vs baseline: 1.2503x; 1.2503x over previous
#include <cuda_runtime.h>
#include <math.h>

#define N_NODES 50000
#define F_IN    128
#define H1      128
#define H2      64
#define E_TRAIN 600000
#define E_SCORE 200000
#define NB_SCAN 196                     // ceil(50000/256)

// Scratch buffers (device globals — no allocation allowed; zero-initialized)
__device__ float g_dinv  [N_NODES];
__device__ int   g_cnt   [N_NODES];               // in-degree; self-zeroed by k_scan
__device__ int   g_rowptr[N_NODES + 1];
__device__ int   g_cursor[N_NODES];
__device__ int   g_ticket;                        // lookback ticket; reset by k_fill
__device__ unsigned long long g_lb[256];          // lookback words (prefix<<2 | status); reset by k_fill
__device__ int   g_esrc  [E_TRAIN];
__device__ float g_h0    [N_NODES * H1];
__device__ float g_agg1  [N_NODES * H1];
__device__ float g_h2p   [N_NODES * H2];
__device__ float g_agg2  [N_NODES * H2];

// ---------------------------------------------------------------- packed f32x2 helpers
__device__ __forceinline__ void fma2(unsigned long long& d,
                                     unsigned long long a,
                                     unsigned long long b) {
    asm("fma.rn.f32x2 %0, %1, %2, %0;" : "+l"(d) : "l"(a), "l"(b));
}
__device__ __forceinline__ float2 u2f(unsigned long long u) {
    float2 f;
    asm("mov.b64 {%0, %1}, %2;" : "=f"(f.x), "=f"(f.y) : "l"(u));
    return f;
}
__device__ __forceinline__ unsigned long long fdup(float a) {
    unsigned long long u;
    asm("mov.b64 %0, {%1, %1};" : "=l"(u) : "f"(a));
    return u;
}

// ---------------------------------------------------------------- count (cnt arrives zeroed)
__global__ void k_count(const int* __restrict__ ei) {
    int e = blockIdx.x * blockDim.x + threadIdx.x;
    if (e < E_TRAIN) atomicAdd(&g_cnt[ei[E_TRAIN + e]], 1);   // col = target
}

// ---------------------------------------------------------------- single-kernel scan (decoupled lookback)
__global__ __launch_bounds__(256) void k_scan() {
    __shared__ int wsum[8];
    __shared__ int sh_bid;
    __shared__ int sh_total;
    __shared__ int sh_exc;
    int t = threadIdx.x;
    if (t == 0) sh_bid = atomicAdd(&g_ticket, 1);
    __syncthreads();
    int bid = sh_bid;
    int i   = bid * 256 + t;

    int v = 0;
    if (i < N_NODES) {
        v = g_cnt[i];
        g_cnt[i] = 0;                               // self-clean for next replay
        g_dinv[i] = rsqrtf((float)(v + 1));
    }
    int s = v;
#pragma unroll
    for (int o = 1; o < 32; o <<= 1) {
        int u = __shfl_up_sync(0xFFFFFFFFu, s, o);
        if ((t & 31) >= o) s += u;
    }
    if ((t & 31) == 31) wsum[t >> 5] = s;
    __syncthreads();
    if (t < 8) {
        int w = wsum[t];
        int e = w;
#pragma unroll
        for (int o = 1; o < 8; o <<= 1) {
            int u = __shfl_up_sync(0xFFu, e, o);
            if (t >= o) e += u;
        }
        wsum[t] = e - w;
    }
    __syncthreads();
    int incl = s + wsum[t >> 5];
    if (t == 255) sh_total = incl;
    __syncthreads();
    int total = sh_total;

    if (t == 0) {
        unsigned long long exc = 0;
        if (bid > 0) {
            atomicExch(&g_lb[bid], ((unsigned long long)total << 2) | 1ull);
            int j = bid - 1;
            while (true) {
                unsigned long long w = atomicAdd(&g_lb[j], 0ull);
                unsigned st = (unsigned)(w & 3ull);
                if (st == 2u) { exc += (w >> 2); break; }
                if (st == 1u) { exc += (w >> 2); j--; }
            }
        }
        atomicExch(&g_lb[bid], ((exc + (unsigned long long)total) << 2) | 2ull);
        sh_exc = (int)exc;
    }
    __syncthreads();
    int exc = sh_exc;
    if (i < N_NODES) {
        int r = exc + incl - v;
        g_rowptr[i] = r;
        g_cursor[i] = r;
    }
    if (i == 0) g_rowptr[N_NODES] = E_TRAIN;
}

// ---------------------------------------------------------------- fill (+ reset lookback state for next replay)
__global__ void k_fill(const int* __restrict__ ei) {
    int gt = blockIdx.x * blockDim.x + threadIdx.x;
    if (blockIdx.x == 0) {
        if (threadIdx.x < NB_SCAN) g_lb[threadIdx.x] = 0ull;
        if (threadIdx.x == NB_SCAN) g_ticket = 0;
    }
    if (gt >= E_TRAIN) return;
    int dst = ei[E_TRAIN + gt];
    int p = atomicAdd(&g_cursor[dst], 1);
    g_esrc[p] = ei[gt];
}

// ---------------------------------------------------------------- GEMM1: g_h0 = x @ W1  [50000x128]@[128x128]
// R9-verbatim: block tile 128x128, thread tile 8x8, packed f32x2, duplicated-x staging.
#define XD_STRIDE 264   // 2*128 + 8 pad
#define WS_STRIDE 136   // 128 + 8 pad
__global__ __launch_bounds__(256) void k_gemm1(const float* __restrict__ x,
                                               const float* __restrict__ W) {
    __shared__ float xdup[16 * XD_STRIDE];
    __shared__ float Ws  [16 * WS_STRIDE];
    const int tx   = threadIdx.x;
    const int tr   = tx >> 4;
    const int tc   = tx & 15;
    const int row0 = blockIdx.x * 128;

    unsigned long long acc[8][4];
#pragma unroll
    for (int r = 0; r < 8; r++)
#pragma unroll
        for (int j = 0; j < 4; j++) acc[r][j] = 0ull;

    for (int k0 = 0; k0 < F_IN; k0 += 16) {
#pragma unroll
        for (int q = 0; q < 2; q++) {
            int idx = tx + 256 * q;
            int row = idx >> 2;
            int kof = (idx & 3) * 4;
            float4 v = make_float4(0.f, 0.f, 0.f, 0.f);
            int grow = row0 + row;
            if (grow < N_NODES) v = *(const float4*)&x[grow * F_IN + k0 + kof];
            *(unsigned long long*)&xdup[(kof + 0) * XD_STRIDE + 2 * row] = fdup(v.x);
            *(unsigned long long*)&xdup[(kof + 1) * XD_STRIDE + 2 * row] = fdup(v.y);
            *(unsigned long long*)&xdup[(kof + 2) * XD_STRIDE + 2 * row] = fdup(v.z);
            *(unsigned long long*)&xdup[(kof + 3) * XD_STRIDE + 2 * row] = fdup(v.w);
        }
#pragma unroll
        for (int q = 0; q < 2; q++) {
            int idx = tx + 256 * q;
            int r = idx >> 5;
            int c = (idx & 31) * 4;
            *(float4*)&Ws[r * WS_STRIDE + c] = *(const float4*)&W[(k0 + r) * H1 + c];
        }
        __syncthreads();

#pragma unroll
        for (int kk = 0; kk < 16; kk++) {
            const ulonglong2* xp = (const ulonglong2*)&xdup[kk * XD_STRIDE + tr * 16];
            unsigned long long xa[8];
#pragma unroll
            for (int i = 0; i < 4; i++) {
                ulonglong2 p = xp[i];
                xa[2 * i + 0] = p.x;
                xa[2 * i + 1] = p.y;
            }
            const ulonglong2* wp = (const ulonglong2*)&Ws[kk * WS_STRIDE + tc * 8];
            ulonglong2 w0 = wp[0], w1 = wp[1];
            unsigned long long wb[4] = { w0.x, w0.y, w1.x, w1.y };
#pragma unroll
            for (int r = 0; r < 8; r++)
#pragma unroll
                for (int j = 0; j < 4; j++)
                    fma2(acc[r][j], xa[r], wb[j]);
        }
        __syncthreads();
    }

#pragma unroll
    for (int r = 0; r < 8; r++) {
        int grow = row0 + tr * 8 + r;
        if (grow < N_NODES) {
            float2 f0 = u2f(acc[r][0]), f1 = u2f(acc[r][1]);
            float2 f2 = u2f(acc[r][2]), f3 = u2f(acc[r][3]);
            float* o = &g_h0[grow * H1 + tc * 8];
            *(float4*)(o + 0) = make_float4(f0.x, f0.y, f1.x, f1.y);
            *(float4*)(o + 4) = make_float4(f2.x, f2.y, f3.x, f3.y);
        }
    }
}

// ---------------------------------------------------------------- agg1 gather: warp per node, 128 feats, unroll 2
__global__ __launch_bounds__(256) void k_agg1_gather(const float* __restrict__ b1) {
    int node = (blockIdx.x * blockDim.x + threadIdx.x) >> 5;
    if (node >= N_NODES) return;
    int lane = threadIdx.x & 31;

    float di = g_dinv[node];
    float selfs = di * di;

    float4 acc = *(const float4*)&g_h0[node * H1 + lane * 4];
    float4 bb  = *(const float4*)&b1[lane * 4];
    acc.x = acc.x * selfs + bb.x;
    acc.y = acc.y * selfs + bb.y;
    acc.z = acc.z * selfs + bb.z;
    acc.w = acc.w * selfs + bb.w;

    int s = g_rowptr[node];
    int e = g_rowptr[node + 1];
    int k = s;
    for (; k + 1 < e; k += 2) {
        int s0 = g_esrc[k], s1 = g_esrc[k + 1];
        float n0 = di * g_dinv[s0];
        float n1 = di * g_dinv[s1];
        float4 v0 = *(const float4*)&g_h0[s0 * H1 + lane * 4];
        float4 v1 = *(const float4*)&g_h0[s1 * H1 + lane * 4];
        acc.x += v0.x * n0 + v1.x * n1;
        acc.y += v0.y * n0 + v1.y * n1;
        acc.z += v0.z * n0 + v1.z * n1;
        acc.w += v0.w * n0 + v1.w * n1;
    }
    if (k < e) {
        int s0 = g_esrc[k];
        float n0 = di * g_dinv[s0];
        float4 v0 = *(const float4*)&g_h0[s0 * H1 + lane * 4];
        acc.x += v0.x * n0; acc.y += v0.y * n0;
        acc.z += v0.z * n0; acc.w += v0.w * n0;
    }
    *(float4*)&g_agg1[node * H1 + lane * 4] = acc;
}

// ---------------------------------------------------------------- GEMM2: g_h2p = relu(g_agg1) @ W2 (R9-verbatim)
#define W2_STRIDE 72   // 64 + 8 pad
__global__ __launch_bounds__(256) void k_gemm2(const float* __restrict__ W2) {
    __shared__ float xdup[16 * XD_STRIDE];
    __shared__ float Ws  [16 * W2_STRIDE];
    const int tx   = threadIdx.x;
    const int tr   = tx >> 4;
    const int tc   = tx & 15;
    const int row0 = blockIdx.x * 128;

    unsigned long long acc[8][2];
#pragma unroll
    for (int r = 0; r < 8; r++) {
        acc[r][0] = 0ull; acc[r][1] = 0ull;
    }

    for (int k0 = 0; k0 < H1; k0 += 16) {
#pragma unroll
        for (int q = 0; q < 2; q++) {
            int idx = tx + 256 * q;
            int row = idx >> 2;
            int kof = (idx & 3) * 4;
            float4 v = make_float4(0.f, 0.f, 0.f, 0.f);
            int grow = row0 + row;
            if (grow < N_NODES) v = *(const float4*)&g_agg1[grow * H1 + k0 + kof];
            *(unsigned long long*)&xdup[(kof + 0) * XD_STRIDE + 2 * row] = fdup(fmaxf(v.x, 0.f));
            *(unsigned long long*)&xdup[(kof + 1) * XD_STRIDE + 2 * row] = fdup(fmaxf(v.y, 0.f));
            *(unsigned long long*)&xdup[(kof + 2) * XD_STRIDE + 2 * row] = fdup(fmaxf(v.z, 0.f));
            *(unsigned long long*)&xdup[(kof + 3) * XD_STRIDE + 2 * row] = fdup(fmaxf(v.w, 0.f));
        }
        {
            int r = tx >> 4;
            int c = (tx & 15) * 4;
            *(float4*)&Ws[r * W2_STRIDE + c] = *(const float4*)&W2[(k0 + r) * H2 + c];
        }
        __syncthreads();

#pragma unroll
        for (int kk = 0; kk < 16; kk++) {
            const ulonglong2* xp = (const ulonglong2*)&xdup[kk * XD_STRIDE + tr * 16];
            unsigned long long xa[8];
#pragma unroll
            for (int i = 0; i < 4; i++) {
                ulonglong2 p = xp[i];
                xa[2 * i + 0] = p.x;
                xa[2 * i + 1] = p.y;
            }
            ulonglong2 w0 = *(const ulonglong2*)&Ws[kk * W2_STRIDE + tc * 4];
            unsigned long long wb0 = w0.x, wb1 = w0.y;
#pragma unroll
            for (int r = 0; r < 8; r++) {
                fma2(acc[r][0], xa[r], wb0);
                fma2(acc[r][1], xa[r], wb1);
            }
        }
        __syncthreads();
    }

#pragma unroll
    for (int r = 0; r < 8; r++) {
        int grow = row0 + tr * 8 + r;
        if (grow < N_NODES) {
            float2 f0 = u2f(acc[r][0]), f1 = u2f(acc[r][1]);
            *(float4*)&g_h2p[grow * H2 + tc * 4] = make_float4(f0.x, f0.y, f1.x, f1.y);
        }
    }
}

// ---------------------------------------------------------------- agg2 gather: half-warp per node, 64 feats, unroll 2
__global__ __launch_bounds__(256) void k_agg2_gather(const float* __restrict__ b2) {
    int node = (blockIdx.x * blockDim.x + threadIdx.x) >> 4;
    if (node >= N_NODES) return;
    int lane = threadIdx.x & 15;

    float di = g_dinv[node];
    float selfs = di * di;

    float4 acc = *(const float4*)&g_h2p[node * H2 + lane * 4];
    float4 bb  = *(const float4*)&b2[lane * 4];
    acc.x = acc.x * selfs + bb.x;
    acc.y = acc.y * selfs + bb.y;
    acc.z = acc.z * selfs + bb.z;
    acc.w = acc.w * selfs + bb.w;

    int s = g_rowptr[node];
    int e = g_rowptr[node + 1];
    int k = s;
    for (; k + 1 < e; k += 2) {
        int s0 = g_esrc[k], s1 = g_esrc[k + 1];
        float n0 = di * g_dinv[s0];
        float n1 = di * g_dinv[s1];
        float4 v0 = *(const float4*)&g_h2p[s0 * H2 + lane * 4];
        float4 v1 = *(const float4*)&g_h2p[s1 * H2 + lane * 4];
        acc.x += v0.x * n0 + v1.x * n1;
        acc.y += v0.y * n0 + v1.y * n1;
        acc.z += v0.z * n0 + v1.z * n1;
        acc.w += v0.w * n0 + v1.w * n1;
    }
    if (k < e) {
        int s0 = g_esrc[k];
        float n0 = di * g_dinv[s0];
        float4 v0 = *(const float4*)&g_h2p[s0 * H2 + lane * 4];
        acc.x += v0.x * n0; acc.y += v0.y * n0;
        acc.z += v0.z * n0; acc.w += v0.w * n0;
    }
    *(float4*)&g_agg2[node * H2 + lane * 4] = acc;
}

// ---------------------------------------------------------------- score: half-warp per edge, dot over 64 dims
__global__ __launch_bounds__(256) void k_score(const int* __restrict__ pos,
                                               const int* __restrict__ neg,
                                               float* __restrict__ out) {
    int w = (blockIdx.x * blockDim.x + threadIdx.x) >> 4;
    if (w >= 2 * E_SCORE) return;
    int lane = threadIdx.x & 15;
    int src, dst;
    if (w < E_SCORE) { src = pos[w];            dst = pos[E_SCORE + w]; }
    else             { int e = w - E_SCORE; src = neg[e]; dst = neg[E_SCORE + e]; }
    float4 a = *(const float4*)&g_agg2[src * H2 + lane * 4];
    float4 b = *(const float4*)&g_agg2[dst * H2 + lane * 4];
    float s = a.x * b.x + a.y * b.y + a.z * b.z + a.w * b.w;
#pragma unroll
    for (int o = 8; o; o >>= 1) s += __shfl_xor_sync(0xFFFFFFFFu, s, o);
    if (lane == 0) out[w] = s;
}

// ----------------------------------------------------------------
extern "C" void kernel_launch(void* const* d_in, const int* in_sizes, int n_in,
                              void* d_out, int out_size) {
    const float* x    = (const float*)d_in[0];
    const int*   tr   = (const int*)  d_in[1];   // [2, 600000]
    const int*   pos  = (const int*)  d_in[2];   // [2, 200000]
    const int*   neg  = (const int*)  d_in[3];   // [2, 200000]
    const float* W1   = (const float*)d_in[4];
    const float* b1   = (const float*)d_in[5];
    const float* W2   = (const float*)d_in[6];
    const float* b2   = (const float*)d_in[7];
    float* out = (float*)d_out;

    // CSR build: count -> single lookback scan -> fill
    k_count<<<(E_TRAIN + 255) / 256, 256>>>(tr);
    k_scan <<<NB_SCAN, 256>>>();
    k_fill <<<(E_TRAIN + 255) / 256, 256>>>(tr);

    // Layer 1
    k_gemm1<<<(N_NODES + 127) / 128, 256>>>(x, W1);
    k_agg1_gather<<<(N_NODES * 32 + 255) / 256, 256>>>(b1);

    // Layer 2
    k_gemm2<<<(N_NODES + 127) / 128, 256>>>(W2);
    k_agg2_gather<<<(N_NODES * 16 + 255) / 256, 256>>>(b2);

    // Scores
    k_score<<<(2 * E_SCORE * 16 + 255) / 256, 256>>>(pos, neg, out);
}

// round 15
// speedup vs baseline: 1.4241x; 1.1390x over previous
#include <cuda_runtime.h>
#include <math.h>

#define N_NODES 50000
#define F_IN    128
#define H1      128
#define H2      64
#define E_TRAIN 600000
#define E_SCORE 200000
#define NB_SCAN 196                     // ceil(50000/256)

// Scratch buffers (device globals — no allocation allowed)
__device__ float g_dinv  [N_NODES];
__device__ int   g_cnt   [N_NODES];
__device__ int   g_rowptr[N_NODES + 1];
__device__ int   g_cursor[N_NODES];
__device__ int   g_bsum  [256];
__device__ int   g_esrc  [E_TRAIN];
__device__ float g_h0    [N_NODES * H1];
__device__ float g_agg1  [N_NODES * H1];
__device__ float g_h2p   [N_NODES * H2];
__device__ float g_agg2  [N_NODES * H2];

// ---------------------------------------------------------------- packed f32x2 helpers
__device__ __forceinline__ void fma2(unsigned long long& d,
                                     unsigned long long a,
                                     unsigned long long b) {
    asm("fma.rn.f32x2 %0, %1, %2, %0;" : "+l"(d) : "l"(a), "l"(b));
}
__device__ __forceinline__ float2 u2f(unsigned long long u) {
    float2 f;
    asm("mov.b64 {%0, %1}, %2;" : "=f"(f.x), "=f"(f.y) : "l"(u));
    return f;
}
__device__ __forceinline__ unsigned long long fdup(float a) {
    unsigned long long u;
    asm("mov.b64 %0, {%1, %1};" : "=l"(u) : "f"(a));
    return u;
}

// ---------------------------------------------------------------- degree/CSR build (R9-verbatim)
__global__ void k_zero_cnt() {
    int i = blockIdx.x * blockDim.x + threadIdx.x;
    if (i < N_NODES) g_cnt[i] = 0;
}

__global__ void k_count(const int* __restrict__ ei) {
    int e = blockIdx.x * blockDim.x + threadIdx.x;
    if (e < E_TRAIN) atomicAdd(&g_cnt[ei[E_TRAIN + e]], 1);   // col = target
}

// Shuffle-based block scan; also emits dinv (fused).
__global__ void k_scan1() {
    __shared__ int wsum[8];
    int t = threadIdx.x;
    int i = blockIdx.x * 256 + t;
    int v = (i < N_NODES) ? g_cnt[i] : 0;
    int s = v;
#pragma unroll
    for (int o = 1; o < 32; o <<= 1) {
        int u = __shfl_up_sync(0xFFFFFFFFu, s, o);
        if ((t & 31) >= o) s += u;
    }
    if ((t & 31) == 31) wsum[t >> 5] = s;
    __syncthreads();
    if (t < 8) {
        int w = wsum[t];
        int e = w;
#pragma unroll
        for (int o = 1; o < 8; o <<= 1) {
            int u = __shfl_up_sync(0xFFu, e, o);
            if (t >= o) e += u;
        }
        wsum[t] = e - w;               // exclusive warp offset
    }
    __syncthreads();
    int incl = s + wsum[t >> 5];
    if (i < N_NODES) {
        g_rowptr[i] = incl - v;        // block-local exclusive
        g_dinv[i]   = rsqrtf((float)(v + 1));
    }
    if (t == 255) g_bsum[blockIdx.x] = incl;
}

// scan3 absorbs scan2: block offset = sum of bsum[0..bid-1] (redundant block reduce).
__global__ void k_scan3() {
    __shared__ int wsum[8];
    __shared__ int total;
    int t   = threadIdx.x;
    int bid = blockIdx.x;
    int v = (t < bid) ? g_bsum[t] : 0;      // bid <= 195 < 256
    int s = v;
#pragma unroll
    for (int o = 16; o; o >>= 1) s += __shfl_xor_sync(0xFFFFFFFFu, s, o);
    if ((t & 31) == 0) wsum[t >> 5] = s;
    __syncthreads();
    if (t == 0) {
        int acc = 0;
#pragma unroll
        for (int w = 0; w < 8; w++) acc += wsum[w];
        total = acc;
    }
    __syncthreads();
    int i = bid * 256 + t;
    if (i < N_NODES) {
        int r = g_rowptr[i] + total;
        g_rowptr[i] = r;
        g_cursor[i] = r;
    }
    if (i == 0) g_rowptr[N_NODES] = E_TRAIN;
}

__global__ void k_fill(const int* __restrict__ ei) {
    int e = blockIdx.x * blockDim.x + threadIdx.x;
    if (e >= E_TRAIN) return;
    int dst = ei[E_TRAIN + e];
    int p = atomicAdd(&g_cursor[dst], 1);
    g_esrc[p] = ei[e];
}

// ---------------------------------------------------------------- GEMM1: g_h0 = x @ W1  (R9-verbatim)
#define XD_STRIDE 264   // 2*128 + 8 pad
#define WS_STRIDE 136   // 128 + 8 pad
__global__ __launch_bounds__(256) void k_gemm1(const float* __restrict__ x,
                                               const float* __restrict__ W) {
    __shared__ float xdup[16 * XD_STRIDE];
    __shared__ float Ws  [16 * WS_STRIDE];
    const int tx   = threadIdx.x;
    const int tr   = tx >> 4;
    const int tc   = tx & 15;
    const int row0 = blockIdx.x * 128;

    unsigned long long acc[8][4];
#pragma unroll
    for (int r = 0; r < 8; r++)
#pragma unroll
        for (int j = 0; j < 4; j++) acc[r][j] = 0ull;

    for (int k0 = 0; k0 < F_IN; k0 += 16) {
#pragma unroll
        for (int q = 0; q < 2; q++) {
            int idx = tx + 256 * q;
            int row = idx >> 2;
            int kof = (idx & 3) * 4;
            float4 v = make_float4(0.f, 0.f, 0.f, 0.f);
            int grow = row0 + row;
            if (grow < N_NODES) v = *(const float4*)&x[grow * F_IN + k0 + kof];
            *(unsigned long long*)&xdup[(kof + 0) * XD_STRIDE + 2 * row] = fdup(v.x);
            *(unsigned long long*)&xdup[(kof + 1) * XD_STRIDE + 2 * row] = fdup(v.y);
            *(unsigned long long*)&xdup[(kof + 2) * XD_STRIDE + 2 * row] = fdup(v.z);
            *(unsigned long long*)&xdup[(kof + 3) * XD_STRIDE + 2 * row] = fdup(v.w);
        }
#pragma unroll
        for (int q = 0; q < 2; q++) {
            int idx = tx + 256 * q;
            int r = idx >> 5;
            int c = (idx & 31) * 4;
            *(float4*)&Ws[r * WS_STRIDE + c] = *(const float4*)&W[(k0 + r) * H1 + c];
        }
        __syncthreads();

#pragma unroll
        for (int kk = 0; kk < 16; kk++) {
            const ulonglong2* xp = (const ulonglong2*)&xdup[kk * XD_STRIDE + tr * 16];
            unsigned long long xa[8];
#pragma unroll
            for (int i = 0; i < 4; i++) {
                ulonglong2 p = xp[i];
                xa[2 * i + 0] = p.x;
                xa[2 * i + 1] = p.y;
            }
            const ulonglong2* wp = (const ulonglong2*)&Ws[kk * WS_STRIDE + tc * 8];
            ulonglong2 w0 = wp[0], w1 = wp[1];
            unsigned long long wb[4] = { w0.x, w0.y, w1.x, w1.y };
#pragma unroll
            for (int r = 0; r < 8; r++)
#pragma unroll
                for (int j = 0; j < 4; j++)
                    fma2(acc[r][j], xa[r], wb[j]);
        }
        __syncthreads();
    }

#pragma unroll
    for (int r = 0; r < 8; r++) {
        int grow = row0 + tr * 8 + r;
        if (grow < N_NODES) {
            float2 f0 = u2f(acc[r][0]), f1 = u2f(acc[r][1]);
            float2 f2 = u2f(acc[r][2]), f3 = u2f(acc[r][3]);
            float* o = &g_h0[grow * H1 + tc * 8];
            *(float4*)(o + 0) = make_float4(f0.x, f0.y, f1.x, f1.y);
            *(float4*)(o + 4) = make_float4(f2.x, f2.y, f3.x, f3.y);
        }
    }
}

// ---------------------------------------------------------------- agg1 gather: warp per node (R9-verbatim)
__global__ __launch_bounds__(256) void k_agg1_gather(const float* __restrict__ b1) {
    int node = (blockIdx.x * blockDim.x + threadIdx.x) >> 5;
    if (node >= N_NODES) return;
    int lane = threadIdx.x & 31;

    float di = g_dinv[node];
    float selfs = di * di;

    float4 acc = *(const float4*)&g_h0[node * H1 + lane * 4];
    float4 bb  = *(const float4*)&b1[lane * 4];
    acc.x = acc.x * selfs + bb.x;
    acc.y = acc.y * selfs + bb.y;
    acc.z = acc.z * selfs + bb.z;
    acc.w = acc.w * selfs + bb.w;

    int s = g_rowptr[node];
    int e = g_rowptr[node + 1];
    for (int k = s; k < e; k++) {
        int src = g_esrc[k];
        float nrm = di * g_dinv[src];
        float4 v = *(const float4*)&g_h0[src * H1 + lane * 4];
        acc.x += v.x * nrm;
        acc.y += v.y * nrm;
        acc.z += v.z * nrm;
        acc.w += v.w * nrm;
    }
    *(float4*)&g_agg1[node * H1 + lane * 4] = acc;
}

// ---------------------------------------------------------------- GEMM2: g_h2p = relu(g_agg1) @ W2 (R9-verbatim)
#define W2_STRIDE 72   // 64 + 8 pad
__global__ __launch_bounds__(256) void k_gemm2(const float* __restrict__ W2) {
    __shared__ float xdup[16 * XD_STRIDE];
    __shared__ float Ws  [16 * W2_STRIDE];
    const int tx   = threadIdx.x;
    const int tr   = tx >> 4;
    const int tc   = tx & 15;
    const int row0 = blockIdx.x * 128;

    unsigned long long acc[8][2];
#pragma unroll
    for (int r = 0; r < 8; r++) {
        acc[r][0] = 0ull; acc[r][1] = 0ull;
    }

    for (int k0 = 0; k0 < H1; k0 += 16) {
#pragma unroll
        for (int q = 0; q < 2; q++) {
            int idx = tx + 256 * q;
            int row = idx >> 2;
            int kof = (idx & 3) * 4;
            float4 v = make_float4(0.f, 0.f, 0.f, 0.f);
            int grow = row0 + row;
            if (grow < N_NODES) v = *(const float4*)&g_agg1[grow * H1 + k0 + kof];
            *(unsigned long long*)&xdup[(kof + 0) * XD_STRIDE + 2 * row] = fdup(fmaxf(v.x, 0.f));
            *(unsigned long long*)&xdup[(kof + 1) * XD_STRIDE + 2 * row] = fdup(fmaxf(v.y, 0.f));
            *(unsigned long long*)&xdup[(kof + 2) * XD_STRIDE + 2 * row] = fdup(fmaxf(v.z, 0.f));
            *(unsigned long long*)&xdup[(kof + 3) * XD_STRIDE + 2 * row] = fdup(fmaxf(v.w, 0.f));
        }
        {
            int r = tx >> 4;
            int c = (tx & 15) * 4;
            *(float4*)&Ws[r * W2_STRIDE + c] = *(const float4*)&W2[(k0 + r) * H2 + c];
        }
        __syncthreads();

#pragma unroll
        for (int kk = 0; kk < 16; kk++) {
            const ulonglong2* xp = (const ulonglong2*)&xdup[kk * XD_STRIDE + tr * 16];
            unsigned long long xa[8];
#pragma unroll
            for (int i = 0; i < 4; i++) {
                ulonglong2 p = xp[i];
                xa[2 * i + 0] = p.x;
                xa[2 * i + 1] = p.y;
            }
            ulonglong2 w0 = *(const ulonglong2*)&Ws[kk * W2_STRIDE + tc * 4];
            unsigned long long wb0 = w0.x, wb1 = w0.y;
#pragma unroll
            for (int r = 0; r < 8; r++) {
                fma2(acc[r][0], xa[r], wb0);
                fma2(acc[r][1], xa[r], wb1);
            }
        }
        __syncthreads();
    }

#pragma unroll
    for (int r = 0; r < 8; r++) {
        int grow = row0 + tr * 8 + r;
        if (grow < N_NODES) {
            float2 f0 = u2f(acc[r][0]), f1 = u2f(acc[r][1]);
            *(float4*)&g_h2p[grow * H2 + tc * 4] = make_float4(f0.x, f0.y, f1.x, f1.y);
        }
    }
}

// ---------------------------------------------------------------- agg2 gather: half-warp per node (R9-verbatim)
__global__ __launch_bounds__(256) void k_agg2_gather(const float* __restrict__ b2) {
    int node = (blockIdx.x * blockDim.x + threadIdx.x) >> 4;
    if (node >= N_NODES) return;
    int lane = threadIdx.x & 15;

    float di = g_dinv[node];
    float selfs = di * di;

    float4 acc = *(const float4*)&g_h2p[node * H2 + lane * 4];
    float4 bb  = *(const float4*)&b2[lane * 4];
    acc.x = acc.x * selfs + bb.x;
    acc.y = acc.y * selfs + bb.y;
    acc.z = acc.z * selfs + bb.z;
    acc.w = acc.w * selfs + bb.w;

    int s = g_rowptr[node];
    int e = g_rowptr[node + 1];
    for (int k = s; k < e; k++) {
        int src = g_esrc[k];
        float nrm = di * g_dinv[src];
        float4 v = *(const float4*)&g_h2p[src * H2 + lane * 4];
        acc.x += v.x * nrm;
        acc.y += v.y * nrm;
        acc.z += v.z * nrm;
        acc.w += v.w * nrm;
    }
    *(float4*)&g_agg2[node * H2 + lane * 4] = acc;
}

// ---------------------------------------------------------------- score: half-warp per edge (R9-verbatim)
__global__ __launch_bounds__(256) void k_score(const int* __restrict__ pos,
                                               const int* __restrict__ neg,
                                               float* __restrict__ out) {
    int w = (blockIdx.x * blockDim.x + threadIdx.x) >> 4;
    if (w >= 2 * E_SCORE) return;
    int lane = threadIdx.x & 15;
    int src, dst;
    if (w < E_SCORE) { src = pos[w];            dst = pos[E_SCORE + w]; }
    else             { int e = w - E_SCORE; src = neg[e]; dst = neg[E_SCORE + e]; }
    float4 a = *(const float4*)&g_agg2[src * H2 + lane * 4];
    float4 b = *(const float4*)&g_agg2[dst * H2 + lane * 4];
    float s = a.x * b.x + a.y * b.y + a.z * b.z + a.w * b.w;
#pragma unroll
    for (int o = 8; o; o >>= 1) s += __shfl_xor_sync(0xFFFFFFFFu, s, o);
    if (lane == 0) out[w] = s;
}

// ----------------------------------------------------------------
// Fork/join: CSR build (side stream) runs concurrently with GEMM1 (main stream);
// they touch disjoint data and join at k_agg1_gather. Handles are created lazily
// on the first (non-captured) correctness call; the captured graph is identical
// on every capture.
extern "C" void kernel_launch(void* const* d_in, const int* in_sizes, int n_in,
                              void* d_out, int out_size) {
    const float* x    = (const float*)d_in[0];
    const int*   tr   = (const int*)  d_in[1];   // [2, 600000]
    const int*   pos  = (const int*)  d_in[2];   // [2, 200000]
    const int*   neg  = (const int*)  d_in[3];   // [2, 200000]
    const float* W1   = (const float*)d_in[4];
    const float* b1   = (const float*)d_in[5];
    const float* W2   = (const float*)d_in[6];
    const float* b2   = (const float*)d_in[7];
    float* out = (float*)d_out;

    static cudaStream_t s2 = nullptr;
    static cudaEvent_t  ev_fork = nullptr, ev_join = nullptr;
    if (s2 == nullptr) {
        cudaStreamCreateWithFlags(&s2, cudaStreamNonBlocking);
        cudaEventCreateWithFlags(&ev_fork, cudaEventDisableTiming);
        cudaEventCreateWithFlags(&ev_join, cudaEventDisableTiming);
    }

    // fork s2 off the main (capture) stream
    cudaEventRecord(ev_fork, 0);
    cudaStreamWaitEvent(s2, ev_fork, 0);

    // CSR build on side stream (independent of gemm1)
    k_zero_cnt<<<(N_NODES + 255) / 256, 256, 0, s2>>>();
    k_count   <<<(E_TRAIN + 255) / 256, 256, 0, s2>>>(tr);
    k_scan1   <<<NB_SCAN, 256, 0, s2>>>();
    k_scan3   <<<NB_SCAN, 256, 0, s2>>>();
    k_fill    <<<(E_TRAIN + 255) / 256, 256, 0, s2>>>(tr);
    cudaEventRecord(ev_join, s2);

    // GEMM1 on main stream, concurrent with CSR build
    k_gemm1<<<(N_NODES + 127) / 128, 256>>>(x, W1);

    // join: agg1 needs both gemm1 (main) and CSR (s2)
    cudaStreamWaitEvent(0, ev_join, 0);
    k_agg1_gather<<<(N_NODES * 32 + 255) / 256, 256>>>(b1);

    // Layer 2 + scores (serial dependency chain)
    k_gemm2<<<(N_NODES + 127) / 128, 256>>>(W2);
    k_agg2_gather<<<(N_NODES * 16 + 255) / 256, 256>>>(b2);
    k_score<<<(2 * E_SCORE * 16 + 255) / 256, 256>>>(pos, neg, out);
}